// round 1
// baseline (speedup 1.0000x reference)
#include <cuda_runtime.h>
#include <cstdint>

// MagNorm: per-channel EMA mean/var over T, normalize each step.
//   mu_t  = a*mu_{t-1} + (1-a)*x_t
//   var_t = a*var_{t-1} + (1-a)*(x_t - mu_t)^2
//   y_t   = (x_t - mu_t) / (sqrt(var_t) + 1e-12)   ~= (x_t-mu_t)*rsqrt(var_t)
//
// Shapes fixed by the problem: x [32, 4096, 481], mu0 [32, 481].
// One thread per (b,f) channel; lane index = f -> coalesced 128B/warp.
// Loads prefetched U ahead (register double buffer) to build MLP ~ 32,
// covering ~577cyc DRAM latency at ~3.3 warps/SM occupancy.

#ifndef MN_B
#define MN_B 32
#define MN_T 4096
#define MN_F 481
#endif

__global__ void __launch_bounds__(32, 32)
magnorm_kernel(const float* __restrict__ x,
               const float* __restrict__ mu0,
               float* __restrict__ out)
{
    constexpr int T = MN_T;
    constexpr int F = MN_F;
    constexpr int U = 32;          // prefetch depth (T % U == 0)

    const int gid = blockIdx.x * blockDim.x + threadIdx.x;
    if (gid >= MN_B * MN_F) return;

    const int b = gid / F;
    const int f = gid - b * F;

    const float a   = 0.99f;       // f32(0.99) — matches JAX weak-type promotion
    const float om  = 0.01f;       // f32(1.0 - 0.99) rounds to f32(0.01)

    float mu  = mu0[gid];
    float var = 1600.0f;           // 40^2

    const size_t base = (size_t)b * T * F + (size_t)f;
    const float* __restrict__ px = x   + base;
    float*       __restrict__ py = out + base;

    // Prologue: prefetch first U timesteps.
    float pre[U];
#pragma unroll
    for (int i = 0; i < U; i++)
        pre[i] = __ldcs(px + (size_t)i * F);
    const float* pnext = px + (size_t)U * F;

    for (int tb = 0; tb < T; tb += U) {
        float cur[U];
#pragma unroll
        for (int i = 0; i < U; i++) cur[i] = pre[i];

        // Kick off next chunk's loads before touching the recurrence so the
        // LDGs overlap the dependent FMA/MUFU chain below.
        if (tb + U < T) {
#pragma unroll
            for (int i = 0; i < U; i++)
                pre[i] = __ldcs(pnext + (size_t)i * F);
            pnext += (size_t)U * F;
        }

#pragma unroll
        for (int i = 0; i < U; i++) {
            mu = fmaf(a, mu, om * cur[i]);
            const float d = cur[i] - mu;
            var = fmaf(a, var, om * (d * d));
            const float y = d * rsqrtf(var);   // eps=1e-12 is negligible vs rel_err 1e-3
            __stcs(py + (size_t)i * F, y);
        }
        py += (size_t)U * F;
    }
}

extern "C" void kernel_launch(void* const* d_in, const int* in_sizes, int n_in,
                              void* d_out, int out_size)
{
    // Inputs per metadata order: x [B,T,F] f32, mu0 [B,F] f32.
    // Be robust to ordering: x is the big one.
    const float* x   = (const float*)d_in[0];
    const float* mu0 = (const float*)d_in[1];
    if (n_in >= 2 && in_sizes[0] < in_sizes[1]) {
        x   = (const float*)d_in[1];
        mu0 = (const float*)d_in[0];
    }
    float* out = (float*)d_out;

    const int channels = MN_B * MN_F;          // 15392
    const int block = 32;                      // 1 warp per block -> spread over all SMs
    const int grid  = (channels + block - 1) / block;  // 481
    magnorm_kernel<<<grid, block>>>(x, mu0, out);
}

// round 2
// speedup vs baseline: 1.4189x; 1.4189x over previous
#include <cuda_runtime.h>
#include <cstdint>

// MagNorm: per-channel EMA mean/var over T, normalize each step.
//   mu_t  = a*mu_{t-1} + (1-a)*x_t
//   var_t = a*var_{t-1} + (1-a)*(x_t - mu_t)^2
//   y_t   = (x_t - mu_t) * rsqrt(var_t)     (eps=1e-12 negligible at 1e-3 tol)
//
// x [32, 4096, 481] f32, mu0 [32, 481] f32. One thread per (b,f) channel.
// Ping-pong register double buffer of depth U=32 keeps a genuine 32-deep
// LDG window in flight (Little's law: 481 warps * 32 * 128B ~ 2MB in flight
// -> DRAM-roofline). NO min-blocks launch bound: that capped regs at 64 in
// R1 and collapsed MLP to ~12 (measured 2.27 TB/s, predicted 2.3).

#ifndef MN_B
#define MN_B 32
#define MN_T 4096
#define MN_F 481
#endif

__global__ void __launch_bounds__(32)
magnorm_kernel(const float* __restrict__ x,
               const float* __restrict__ mu0,
               float* __restrict__ out)
{
    constexpr int T = MN_T;
    constexpr int F = MN_F;
    constexpr int U = 32;           // buffer depth; T % (2U) == 0

    const int gid = blockIdx.x * blockDim.x + threadIdx.x;
    if (gid >= MN_B * MN_F) return;

    const int b = gid / F;
    const int f = gid - b * F;

    const float a  = 0.99f;
    const float om = 0.01f;

    float mu  = mu0[gid];
    float var = 1600.0f;            // 40^2

    const size_t base = (size_t)b * T * F + (size_t)f;
    const float* __restrict__ px = x   + base;
    float*       __restrict__ py = out + base;

    float bufA[U], bufB[U];

    // Prologue: fill A with t = 0..U-1.
#pragma unroll
    for (int i = 0; i < U; i++)
        bufA[i] = __ldcs(px + (size_t)i * F);
    const float* pn = px + (size_t)U * F;

    for (int tb = 0; tb < T; tb += 2 * U) {
        // Loads for B (t = tb+U .. tb+2U-1). Always in range since T % 2U == 0.
#pragma unroll
        for (int i = 0; i < U; i++)
            bufB[i] = __ldcs(pn + (size_t)i * F);
        pn += (size_t)U * F;

        // Compute + store A while B's loads are in flight.
#pragma unroll
        for (int i = 0; i < U; i++) {
            mu = fmaf(a, mu, om * bufA[i]);
            const float d = bufA[i] - mu;
            var = fmaf(a, var, om * (d * d));
            __stcs(py + (size_t)i * F, d * rsqrtf(var));
        }
        py += (size_t)U * F;

        // Loads for next A (t = tb+2U ..), skipped on the final iteration.
        if (tb + 2 * U < T) {
#pragma unroll
            for (int i = 0; i < U; i++)
                bufA[i] = __ldcs(pn + (size_t)i * F);
            pn += (size_t)U * F;
        }

        // Compute + store B while A's loads are in flight.
#pragma unroll
        for (int i = 0; i < U; i++) {
            mu = fmaf(a, mu, om * bufB[i]);
            const float d = bufB[i] - mu;
            var = fmaf(a, var, om * (d * d));
            __stcs(py + (size_t)i * F, d * rsqrtf(var));
        }
        py += (size_t)U * F;
    }
}

extern "C" void kernel_launch(void* const* d_in, const int* in_sizes, int n_in,
                              void* d_out, int out_size)
{
    const float* x   = (const float*)d_in[0];
    const float* mu0 = (const float*)d_in[1];
    if (n_in >= 2 && in_sizes[0] < in_sizes[1]) {
        x   = (const float*)d_in[1];
        mu0 = (const float*)d_in[0];
    }
    float* out = (float*)d_out;

    const int channels = MN_B * MN_F;                  // 15392
    const int block = 32;                              // 1 warp/block -> spread over SMs
    const int grid  = (channels + block - 1) / block;  // 481
    magnorm_kernel<<<grid, block>>>(x, mu0, out);
}

// round 3
// speedup vs baseline: 1.7157x; 1.2091x over previous
#include <cuda_runtime.h>
#include <cstdint>

// MagNorm: per-channel EMA mean/var over T, normalize each step.
//   mu_t  = a*mu_{t-1} + (1-a)*x_t
//   var_t = a*var_{t-1} + (1-a)*(x_t - mu_t)^2
//   y_t   = (x_t - mu_t) * rsqrt(var_t)     (eps=1e-12 negligible at 1e-3 tol)
//
// x [32, 4096, 481] f32, mu0 [32, 481] f32. One thread per (b,f) channel,
// lane = f -> coalesced 128B/warp.
//
// R2 post-mortem: double buffer = 1-chunk lookahead (~300-420 cyc) < DRAM
// latency under load (~600-700 cyc) -> 66 cyc/elem, latency-bound at 3.2TB/s.
// R3: QUAD buffer -> 3-chunk prefetch distance (~1260 cyc) fully covers
// latency; per-warp rate becomes issue-bound (~13 cyc/elem) and the chip
// should hit the DRAM roofline. 128 data regs + ~20 overhead, fine at
// 1 warp/block (255-reg cap, no min-blocks clause!).

#ifndef MN_B
#define MN_B 32
#define MN_T 4096
#define MN_F 481
#endif

__global__ void __launch_bounds__(32)
magnorm_kernel(const float* __restrict__ x,
               const float* __restrict__ mu0,
               float* __restrict__ out)
{
    constexpr int T   = MN_T;
    constexpr int F   = MN_F;
    constexpr int U   = 32;              // chunk size
    constexpr int NB  = 4;               // buffers (prefetch distance NB-1)
    constexpr int NCH = T / U;           // 128 chunks, NCH % NB == 0

    const int gid = blockIdx.x * blockDim.x + threadIdx.x;
    if (gid >= MN_B * MN_F) return;

    const int b = gid / F;
    const int f = gid - b * F;

    const float a  = 0.99f;
    const float om = 0.01f;

    float mu  = mu0[gid];
    float var = 1600.0f;                 // 40^2

    const size_t base = (size_t)b * T * F + (size_t)f;
    const float* __restrict__ px = x   + base;
    float*       __restrict__ py = out + base;

    float buf[NB][U];                    // static indexing only -> registers

    // Prologue: prefetch chunks 0 .. NB-2 into buffers 0 .. NB-2.
    const float* pn = px;
#pragma unroll
    for (int s = 0; s < NB - 1; s++) {
#pragma unroll
        for (int i = 0; i < U; i++)
            buf[s][i] = __ldcs(pn + (size_t)i * F);
        pn += (size_t)U * F;
    }

    int loaded = NB - 1;                 // next chunk index to load
    for (int g = 0; g < NCH; g += NB) {
#pragma unroll
        for (int s = 0; s < NB; s++) {
            // Issue loads for chunk (g + s + NB - 1) into the buffer that was
            // just freed last stage: slot (s + NB - 1) % NB. Keeps NB-1 chunks
            // of LDGs in flight ahead of the consumer at all times.
            constexpr int ls = (NB - 1);  // lookahead in chunks
            if (g + s + ls < NCH) {
#pragma unroll
                for (int i = 0; i < U; i++)
                    buf[(s + ls) % NB][i] = __ldcs(pn + (size_t)i * F);
                pn += (size_t)U * F;
                loaded++;
            }

            // Consume chunk g + s from buffer s while the above loads fly.
#pragma unroll
            for (int i = 0; i < U; i++) {
                const float xv = buf[s][i];
                mu = fmaf(a, mu, om * xv);
                const float d = xv - mu;
                var = fmaf(a, var, om * (d * d));
                __stcs(py + (size_t)i * F, d * rsqrtf(var));
            }
            py += (size_t)U * F;
        }
    }
    (void)loaded;
}

extern "C" void kernel_launch(void* const* d_in, const int* in_sizes, int n_in,
                              void* d_out, int out_size)
{
    const float* x   = (const float*)d_in[0];
    const float* mu0 = (const float*)d_in[1];
    if (n_in >= 2 && in_sizes[0] < in_sizes[1]) {
        x   = (const float*)d_in[1];
        mu0 = (const float*)d_in[0];
    }
    float* out = (float*)d_out;

    const int channels = MN_B * MN_F;                  // 15392
    const int block = 32;                              // 1 warp/block
    const int grid  = (channels + block - 1) / block;  // 481
    magnorm_kernel<<<grid, block>>>(x, mu0, out);
}